// round 8
// baseline (speedup 1.0000x reference)
#include <cuda_runtime.h>
#include <cuda_fp16.h>
#include <cuda_bf16.h>
#include <math.h>
#include <stdint.h>

#define G     128
#define NPG   256
#define DF    128
#define KB    16
#define NB    11          // bins 0..10 (rest < e^-12, left zero)
#define NTILE 36          // upper-tri 32x32 tiles
#define TILE_HALVES 1024
#define NU4   (NTILE * 128)   // 4608 uint4 chunks per CTA = 18*256

// ---- device scratch ----
__device__ float    g_sig[2 * G * KB];
__device__ float    g_rowloss[2 * G];
__device__ __half   g_Ds[256 * NTILE * TILE_HALVES];   // 18MB, fragment-native layout
__device__ unsigned g_ctr = 0;

// diag tile slots: b(b+3)/2 for b=0..7 -> {0,2,5,9,14,20,27,35}
#define DIAGMASK 0x808104225ULL

// ---- smem layout (bytes) ----
#define HS_STRIDE_B 272
#define OFF_SQ   (NPG * HS_STRIDE_B)
#define OFF_ZR   (OFF_SQ + NPG * 4)
#define OFF_RED  (OFF_ZR + DF * 4)
#define SMEM_A   (OFF_RED + 128 * 4)         // ~70KB -> 2 CTAs/SM

__device__ __forceinline__ float sqrt_ap(float x) {
    float y; asm("sqrt.approx.ftz.f32 %0, %1;" : "=f"(y) : "f"(x)); return y;
}
__device__ __forceinline__ __half2 h2ex2(__half2 x) {
    uint32_t xi = *(uint32_t*)&x, yi;
    asm("ex2.approx.f16x2 %0, %1;" : "=r"(yi) : "r"(xi));
    return *(__half2*)&yi;
}
__device__ __forceinline__ void ldmx4(uint32_t& r0, uint32_t& r1, uint32_t& r2, uint32_t& r3, uint32_t addr) {
    asm volatile("ldmatrix.sync.aligned.m8n8.x4.shared.b16 {%0,%1,%2,%3}, [%4];"
                 : "=r"(r0), "=r"(r1), "=r"(r2), "=r"(r3) : "r"(addr));
}
__device__ __forceinline__ void mma_bf16(float& c0, float& c1, float& c2, float& c3,
                                         uint32_t a0, uint32_t a1, uint32_t a2, uint32_t a3,
                                         uint32_t b0, uint32_t b1) {
    asm volatile("mma.sync.aligned.m16n8k16.row.col.f32.bf16.bf16.f32 "
                 "{%0,%1,%2,%3}, {%4,%5,%6,%7}, {%8,%9}, {%0,%1,%2,%3};"
                 : "+f"(c0), "+f"(c1), "+f"(c2), "+f"(c3)
                 : "r"(a0), "r"(a1), "r"(a2), "r"(a3), "r"(b0), "r"(b1));
}

// One CTA per (view, graph). 256 threads = 8 warps. 2 CTAs/SM.
__global__ void __launch_bounds__(256, 2)
uts_kernel(const float* __restrict__ H1, const float* __restrict__ H2,
           const float* __restrict__ z1, const float* __restrict__ z2,
           float* __restrict__ out)
{
    const int bx = blockIdx.x;
    const int v  = bx >> 7;
    const int g  = bx & (G - 1);
    const float* __restrict__ H = (v ? H2 : H1) + (size_t)g * NPG * DF;
    __half* __restrict__ Dg = g_Ds + (size_t)bx * (NTILE * TILE_HALVES);

    extern __shared__ char sraw[];
    char*  Hs  = sraw;
    float* sq  = (float*)(sraw + OFF_SQ);
    float* zr  = (float*)(sraw + OFF_ZR);
    float* red = (float*)(sraw + OFF_RED);

    const int tid  = threadIdx.x;
    const int lane = tid & 31;
    const int wid  = tid >> 5;
    const uint32_t hs_base = (uint32_t)__cvta_generic_to_shared(Hs);

    // ================== load H -> bf16 smem + sq ==================
    {
        const float4* __restrict__ Hp = (const float4*)H;
        #pragma unroll
        for (int it = 0; it < 16; it++) {
            int id = it * 256 + tid;
            int n  = id >> 4;
            int c  = id & 15;
            float4 f0 = Hp[n * 32 + 2 * c];
            float4 f1 = Hp[n * 32 + 2 * c + 1];
            __nv_bfloat162 b0 = __float22bfloat162_rn(make_float2(f0.x, f0.y));
            __nv_bfloat162 b1 = __float22bfloat162_rn(make_float2(f0.z, f0.w));
            __nv_bfloat162 b2 = __float22bfloat162_rn(make_float2(f1.x, f1.y));
            __nv_bfloat162 b3 = __float22bfloat162_rn(make_float2(f1.z, f1.w));
            uint4 pk;
            pk.x = *(uint32_t*)&b0; pk.y = *(uint32_t*)&b1;
            pk.z = *(uint32_t*)&b2; pk.w = *(uint32_t*)&b3;
            *(uint4*)(Hs + n * HS_STRIDE_B + c * 16) = pk;
            float2 r0 = __bfloat1622float2(b0), r1 = __bfloat1622float2(b1);
            float2 r2 = __bfloat1622float2(b2), r3 = __bfloat1622float2(b3);
            float s = r0.x*r0.x + r0.y*r0.y + r1.x*r1.x + r1.y*r1.y
                    + r2.x*r2.x + r2.y*r2.y + r3.x*r3.x + r3.y*r3.y;
            #pragma unroll
            for (int o = 1; o < 16; o <<= 1) s += __shfl_xor_sync(0xffffffffu, s, o);
            if ((tid & 15) == 0) sq[n] = s;
        }
    }
    __syncthreads();

    // ================== pass 1: upper-tri Gram -> d (fragment-native fp16 global), sumD ==========
    float sumD = 0.f;
    {
        const int b  = (wid < 4) ? wid : 11 - wid;   // col block; SMSP-balanced
        const int j0 = b * 32;
        const int slotBase = b * (b + 1) / 2;
        const int gq = lane >> 2, tq = lane & 3;
        const int arow_l = lane & 15, asel = lane >> 4;
        const int brow_l = (lane & 7) + ((lane & 16) >> 1);
        const int bsel   = (lane >> 3) & 1;

        for (int rt = 0; rt <= b; rt++) {
            const int i0 = rt * 32;
            float c[2][4][4];
            #pragma unroll
            for (int ms = 0; ms < 2; ms++)
                #pragma unroll
                for (int ns = 0; ns < 4; ns++)
                    #pragma unroll
                    for (int q = 0; q < 4; q++) c[ms][ns][q] = 0.f;

            #pragma unroll
            for (int s = 0; s < 8; s++) {
                uint32_t A[2][4];
                #pragma unroll
                for (int ms = 0; ms < 2; ms++) {
                    uint32_t addr = hs_base + (uint32_t)((i0 + ms * 16 + arow_l) * HS_STRIDE_B
                                                         + (2 * s + asel) * 16);
                    ldmx4(A[ms][0], A[ms][1], A[ms][2], A[ms][3], addr);
                }
                uint32_t B[2][4];
                #pragma unroll
                for (int nbp = 0; nbp < 2; nbp++) {
                    uint32_t addr = hs_base + (uint32_t)((j0 + nbp * 16 + brow_l) * HS_STRIDE_B
                                                         + (2 * s + bsel) * 16);
                    ldmx4(B[nbp][0], B[nbp][1], B[nbp][2], B[nbp][3], addr);
                }
                #pragma unroll
                for (int ms = 0; ms < 2; ms++)
                    #pragma unroll
                    for (int ns = 0; ns < 4; ns++) {
                        uint32_t bb0 = B[ns >> 1][(ns & 1) ? 2 : 0];
                        uint32_t bb1 = B[ns >> 1][(ns & 1) ? 3 : 1];
                        mma_bf16(c[ms][ns][0], c[ms][ns][1], c[ms][ns][2], c[ms][ns][3],
                                 A[ms][0], A[ms][1], A[ms][2], A[ms][3], bb0, bb1);
                    }
            }

            // epilogue: fragment-native store (coalesced), weighted sumD
            __half* tptr = Dg + (slotBase + rt) * TILE_HALVES;
            #pragma unroll
            for (int ms = 0; ms < 2; ms++) {
                #pragma unroll
                for (int ns = 0; ns < 4; ns++) {
                    const int i  = i0 + ms * 16 + gq;
                    const int j  = j0 + ns * 8 + 2 * tq;
                    const float sj0 = sq[j], sj1 = sq[j + 1];
                    const float si  = sq[i];
                    const float si8 = sq[i + 8];
                    float d0 = sqrt_ap(fmaxf(si  + sj0 - 2.f * c[ms][ns][0], 0.f) + 1e-12f);
                    float d1 = sqrt_ap(fmaxf(si  + sj1 - 2.f * c[ms][ns][1], 0.f) + 1e-12f);
                    float d2 = sqrt_ap(fmaxf(si8 + sj0 - 2.f * c[ms][ns][2], 0.f) + 1e-12f);
                    float d3 = sqrt_ap(fmaxf(si8 + sj1 - 2.f * c[ms][ns][3], 0.f) + 1e-12f);
                    const int f0 = ms * 8 + ns * 2;       // h=0
                    *(__half2*)&tptr[f0 * 64 + lane * 2]       = __floats2half2_rn(d0, d1);
                    *(__half2*)&tptr[(f0 + 1) * 64 + lane * 2] = __floats2half2_rn(d2, d3);
                    if (rt < b) {
                        sumD += 2.f * (d0 + d1 + d2 + d3);
                    } else {
                        if (j     > i) sumD += 2.f * d0; else if (j     == i) sumD += d0;
                        if (j + 1 > i) sumD += 2.f * d1; else if (j + 1 == i) sumD += d1;
                        if (j     > i + 8) sumD += 2.f * d2; else if (j     == i + 8) sumD += d2;
                        if (j + 1 > i + 8) sumD += 2.f * d3; else if (j + 1 == i + 8) sumD += d3;
                    }
                }
            }
        }
    }

    // reduce sumD
    #pragma unroll
    for (int o = 16; o; o >>= 1) sumD += __shfl_xor_sync(0xffffffffu, sumD, o);
    if (lane == 0) red[wid] = sumD;
    __syncthreads();   // also makes Dg writes visible CTA-wide
    float meanD = 0.f;
    #pragma unroll
    for (int w = 0; w < 8; w++) meanD += red[w];
    meanD *= (1.f / 65536.f);

    // ================== pass 2: fragment-order coalesced, packed fp16 center-out chain ==========
    const float invf = 1.f / ((meanD + 1e-8f) * 0.1875f);
    const __half2 inv2  = __float2half2_rn(invf);
    const __half2 off2  = __float2half2_rn(-5.3333333f);
    const __half2 A2    = __float2half2_rn(-0.72134752f);
    const __half2 RHO2  = __float2half2_rn(1.53887471f);
    const __half2 ONE2  = __float2half2_rn(1.0f);
    const __half2 UMAX2 = __float2half2_rn(5.4f);
    const __half2 UMIN2 = __float2half2_rn(-5.4f);
    // step ratio m=1..5: 2^{-0.820734*(2m-1)}
    const __half2 RS2[5] = { __float2half2_rn(0.566155f),  __float2half2_rn(0.181456f),
                             __float2half2_rn(0.0581705f), __float2half2_rn(0.0186443f),
                             __float2half2_rn(0.00597603f) };

    float histf[NB];
    #pragma unroll
    for (int k = 0; k < NB; k++) histf[k] = 0.f;

    {
        const char* Dgb = (const char*)Dg;
        uint4 vv = *(const uint4*)(Dgb + tid * 16);          // prefetch it=0
        for (int it = 0; it < 18; it++) {                    // 18*256 = 4608 exactly
            const int w = it * 256 + tid;
            uint4 cur = vv;
            if (it < 17)
                vv = *(const uint4*)(Dgb + (w + 256) * 16);  // prefetch next

            const int tile = w >> 7;
            __half2 wl[4];
            if ((DIAGMASK >> tile) & 1ULL) {
                // diag tile: reconstruct (i_rel, j_rel) from fragment coords
                const int m  = w & 127;
                const int f  = m >> 3;
                const int lg = m & 7;                        // = lane>>2 of producing lanes
                const int ms = f >> 3, ns = (f >> 1) & 3, h = f & 1;
                const int irel = ms * 16 + lg + 8 * h;
                const int jb   = ns * 8;
                #pragma unroll
                for (int e = 0; e < 4; e++) {
                    const int jl = jb + 2 * e;
                    float wlo = (jl     > irel) ? 1.f : ((jl     == irel) ? 0.f : -300.f);
                    float whi = (jl + 1 > irel) ? 1.f : ((jl + 1 == irel) ? 0.f : -300.f);
                    wl[e] = __floats2half2_rn(wlo, whi);
                }
            } else {
                #pragma unroll
                for (int e = 0; e < 4; e++) wl[e] = ONE2;    // weight 2 (log2 = 1)
            }

            __half2 dd[4] = { *(__half2*)&cur.x, *(__half2*)&cur.y,
                              *(__half2*)&cur.z, *(__half2*)&cur.w };
            __half2 h2a[NB];
            #pragma unroll
            for (int k = 0; k < NB; k++) h2a[k] = __float2half2_rn(0.f);

            #pragma unroll
            for (int e = 0; e < 4; e++) {
                __half2 u2 = __hfma2(dd[e], inv2, off2);
                u2 = __hmax2(__hmin2(u2, UMAX2), UMIN2);
                __half2 us = __hmul2(u2, u2);
                __half2 e0 = __hfma2(us, A2, wl[e]);
                __half2 w5 = h2ex2(e0);
                __half2 pu = __hmul2(u2, RHO2);
                __half2 P  = h2ex2(pu);
                __half2 Pi = h2ex2(__hneg2(pu));
                h2a[5] = __hadd2(h2a[5], w5);
                __half2 rr = w5;
                #pragma unroll
                for (int m2 = 0; m2 < 5; m2++) {
                    rr = __hmul2(__hmul2(rr, Pi), RS2[m2]);
                    h2a[4 - m2] = __hadd2(h2a[4 - m2], rr);
                }
                rr = w5;
                #pragma unroll
                for (int m2 = 0; m2 < 5; m2++) {
                    rr = __hmul2(__hmul2(rr, P), RS2[m2]);
                    h2a[6 + m2] = __hadd2(h2a[6 + m2], rr);
                }
            }
            #pragma unroll
            for (int k = 0; k < NB; k++) {
                float2 t = __half22float2(h2a[k]);
                histf[k] += t.x + t.y;
            }
        }
    }

    // reduce hist, write signature
    #pragma unroll
    for (int k = 0; k < NB; k++)
        #pragma unroll
        for (int o = 16; o; o >>= 1)
            histf[k] += __shfl_xor_sync(0xffffffffu, histf[k], o);
    if (lane == 0) {
        #pragma unroll
        for (int k = 0; k < NB; k++) red[8 + wid * NB + k] = histf[k];
    }
    __syncthreads();

    if (tid < KB) {
        float h = 0.f;
        if (tid < NB) {
            #pragma unroll
            for (int w = 0; w < 8; w++) h += red[8 + w * NB + tid];
        }
        float tot = h;
        #pragma unroll
        for (int o = 8; o; o >>= 1) tot += __shfl_xor_sync(0x0000ffffu, tot, o);
        g_sig[bx * KB + tid] = h / (tot + 1e-8f);
    }
    __syncthreads();

    // ================== NT-Xent row bx ==================
    {
        float* invn = sq;
        const float* zp = (tid < G) ? (z1 + tid * DF) : (z2 + (tid - G) * DF);
        const float4* zp4 = (const float4*)zp;
        float s = 0.f;
        #pragma unroll 8
        for (int k = 0; k < 32; k++) {
            float4 a = zp4[k];
            s = fmaf(a.x, a.x, fmaf(a.y, a.y, fmaf(a.z, a.z, fmaf(a.w, a.w, s))));
        }
        invn[tid] = 1.f / (sqrtf(s) + 1e-8f);

        const float* zrp = (bx < G) ? (z1 + bx * DF) : (z2 + (bx - G) * DF);
        if (tid < 32) ((float4*)zr)[tid] = ((const float4*)zrp)[tid];
        __syncthreads();

        float dot = 0.f;
        const float4* zr4 = (const float4*)zr;
        #pragma unroll 8
        for (int k = 0; k < 32; k++) {
            float4 a = zp4[k], b2 = zr4[k];
            dot = fmaf(a.x, b2.x, fmaf(a.y, b2.y, fmaf(a.z, b2.z, fmaf(a.w, b2.w, dot))));
        }
        float sim = dot * invn[bx] * invn[tid] * 2.0f;
        const int lbl = bx ^ G;
        if (tid == lbl) red[120] = sim;

        float e = (tid == bx) ? 0.f : __expf(sim);
        #pragma unroll
        for (int o = 16; o; o >>= 1) e += __shfl_xor_sync(0xffffffffu, e, o);
        __syncthreads();
        if (lane == 0) red[wid] = e;
        __syncthreads();
        if (tid == 0) {
            float S = 0.f;
            #pragma unroll
            for (int w = 0; w < 8; w++) S += red[w];
            g_rowloss[bx] = __logf(S) - red[120];
        }
    }

    // ================== last CTA: final reduction ==================
    __shared__ unsigned amLast;
    __syncthreads();
    if (tid == 0) {
        __threadfence();
        unsigned vv = atomicInc(&g_ctr, 255);
        amLast = (vv == 255) ? 1u : 0u;
    }
    __syncthreads();

    if (amLast) {
        __threadfence();
        float a = 0.f;
        for (int idx = tid; idx < G * KB; idx += 256) {
            float d = g_sig[idx] - g_sig[G * KB + idx];
            a += d * d;
        }
        a *= (1.f / 2048.f);
        a += g_rowloss[tid] * (1.f / 256.f);
        #pragma unroll
        for (int o = 16; o; o >>= 1) a += __shfl_xor_sync(0xffffffffu, a, o);
        if (lane == 0) red[64 + wid] = a;
        __syncthreads();
        if (tid == 0) {
            float t = 0.f;
            #pragma unroll
            for (int w = 0; w < 8; w++) t += red[64 + w];
            out[0] = 0.1f * t;
        }
    }
}

extern "C" void kernel_launch(void* const* d_in, const int* in_sizes, int n_in,
                              void* d_out, int out_size)
{
    const float* H1 = (const float*)d_in[0];
    const float* H2 = (const float*)d_in[2];
    const float* z1 = (const float*)d_in[4];
    const float* z2 = (const float*)d_in[5];
    float* out = (float*)d_out;

    cudaFuncSetAttribute(uts_kernel, cudaFuncAttributeMaxDynamicSharedMemorySize, SMEM_A);
    uts_kernel<<<256, 256, SMEM_A>>>(H1, H2, z1, z2, out);
}

// round 9
// speedup vs baseline: 1.3066x; 1.3066x over previous
#include <cuda_runtime.h>
#include <cuda_fp16.h>
#include <cuda_bf16.h>
#include <math.h>
#include <stdint.h>

#define G     128
#define NPG   256
#define DF    128
#define KB    16
#define NB    11          // bins 0..10 (rest < e^-12, left zero)
#define NCHUNK 4224       // 16B chunks covering upper triangle (incl. alignment slack)

// ---- device scratch ----
__device__ float    g_sig[2 * G * KB];
__device__ float    g_rowloss[2 * G];
__device__ __half   g_Ds[256 * NPG * NPG];   // 33.5MB distance scratch
__device__ unsigned g_ctr = 0;

// ---- smem layout (bytes) ----
#define HS_STRIDE_B 272
#define OFF_SQ   (NPG * HS_STRIDE_B)
#define OFF_ZR   (OFF_SQ + NPG * 4)
#define OFF_RED  (OFF_ZR + DF * 4)
#define SMEM_A   (OFF_RED + 128 * 4)         // ~70KB -> 2 CTAs/SM

__device__ __forceinline__ float sqrt_ap(float x) {
    float y; asm("sqrt.approx.ftz.f32 %0, %1;" : "=f"(y) : "f"(x)); return y;
}
__device__ __forceinline__ __half2 h2ex2(__half2 x) {
    uint32_t xi = *(uint32_t*)&x, yi;
    asm("ex2.approx.f16x2 %0, %1;" : "=r"(yi) : "r"(xi));
    return *(__half2*)&yi;
}
__device__ __forceinline__ void ldmx4(uint32_t& r0, uint32_t& r1, uint32_t& r2, uint32_t& r3, uint32_t addr) {
    asm volatile("ldmatrix.sync.aligned.m8n8.x4.shared.b16 {%0,%1,%2,%3}, [%4];"
                 : "=r"(r0), "=r"(r1), "=r"(r2), "=r"(r3) : "r"(addr));
}
__device__ __forceinline__ void mma_bf16(float& c0, float& c1, float& c2, float& c3,
                                         uint32_t a0, uint32_t a1, uint32_t a2, uint32_t a3,
                                         uint32_t b0, uint32_t b1) {
    asm volatile("mma.sync.aligned.m16n8k16.row.col.f32.bf16.bf16.f32 "
                 "{%0,%1,%2,%3}, {%4,%5,%6,%7}, {%8,%9}, {%0,%1,%2,%3};"
                 : "+f"(c0), "+f"(c1), "+f"(c2), "+f"(c3)
                 : "r"(a0), "r"(a1), "r"(a2), "r"(a3), "r"(b0), "r"(b1));
}

// One CTA per (view, graph). 256 threads = 8 warps. 2 CTAs/SM.
__global__ void __launch_bounds__(256, 2)
uts_kernel(const float* __restrict__ H1, const float* __restrict__ H2,
           const float* __restrict__ z1, const float* __restrict__ z2,
           float* __restrict__ out)
{
    const int bx = blockIdx.x;
    const int v  = bx >> 7;
    const int g  = bx & (G - 1);
    const float* __restrict__ H = (v ? H2 : H1) + (size_t)g * NPG * DF;
    __half* __restrict__ Dg = g_Ds + (size_t)bx * (NPG * NPG);

    extern __shared__ char sraw[];
    char*  Hs  = sraw;
    float* sq  = (float*)(sraw + OFF_SQ);
    float* zr  = (float*)(sraw + OFF_ZR);
    float* red = (float*)(sraw + OFF_RED);

    const int tid  = threadIdx.x;
    const int lane = tid & 31;
    const int wid  = tid >> 5;
    const uint32_t hs_base = (uint32_t)__cvta_generic_to_shared(Hs);

    // ================== load H -> bf16 smem + sq ==================
    {
        const float4* __restrict__ Hp = (const float4*)H;
        #pragma unroll
        for (int it = 0; it < 16; it++) {
            int id = it * 256 + tid;
            int n  = id >> 4;
            int c  = id & 15;
            float4 f0 = Hp[n * 32 + 2 * c];
            float4 f1 = Hp[n * 32 + 2 * c + 1];
            __nv_bfloat162 b0 = __float22bfloat162_rn(make_float2(f0.x, f0.y));
            __nv_bfloat162 b1 = __float22bfloat162_rn(make_float2(f0.z, f0.w));
            __nv_bfloat162 b2 = __float22bfloat162_rn(make_float2(f1.x, f1.y));
            __nv_bfloat162 b3 = __float22bfloat162_rn(make_float2(f1.z, f1.w));
            uint4 pk;
            pk.x = *(uint32_t*)&b0; pk.y = *(uint32_t*)&b1;
            pk.z = *(uint32_t*)&b2; pk.w = *(uint32_t*)&b3;
            *(uint4*)(Hs + n * HS_STRIDE_B + c * 16) = pk;
            float2 r0 = __bfloat1622float2(b0), r1 = __bfloat1622float2(b1);
            float2 r2 = __bfloat1622float2(b2), r3 = __bfloat1622float2(b3);
            float s = r0.x*r0.x + r0.y*r0.y + r1.x*r1.x + r1.y*r1.y
                    + r2.x*r2.x + r2.y*r2.y + r3.x*r3.x + r3.y*r3.y;
            #pragma unroll
            for (int o = 1; o < 16; o <<= 1) s += __shfl_xor_sync(0xffffffffu, s, o);
            if ((tid & 15) == 0) sq[n] = s;
        }
    }
    __syncthreads();

    // ================== pass 1: upper-tri Gram -> d (fp16 global), sumD ==================
    float sumD = 0.f;
    {
        const int b  = (wid < 4) ? wid : 11 - wid;   // col block; SMSP-balanced
        const int j0 = b * 32;
        const int gq = lane >> 2, tq = lane & 3;
        const int arow_l = lane & 15, asel = lane >> 4;
        const int brow_l = (lane & 7) + ((lane & 16) >> 1);
        const int bsel   = (lane >> 3) & 1;

        // B fragments are invariant across the rt loop (col block fixed per warp): hoist
        uint32_t Ball[8][8];   // [s][nbp*4 + k]
        #pragma unroll
        for (int s = 0; s < 8; s++) {
            #pragma unroll
            for (int nbp = 0; nbp < 2; nbp++) {
                uint32_t addr = hs_base + (uint32_t)((j0 + nbp * 16 + brow_l) * HS_STRIDE_B
                                                     + (2 * s + bsel) * 16);
                ldmx4(Ball[s][nbp * 4 + 0], Ball[s][nbp * 4 + 1],
                      Ball[s][nbp * 4 + 2], Ball[s][nbp * 4 + 3], addr);
            }
        }

        for (int rt = 0; rt <= b; rt++) {
            const int i0 = rt * 32;
            float c[2][4][4];
            #pragma unroll
            for (int ms = 0; ms < 2; ms++)
                #pragma unroll
                for (int ns = 0; ns < 4; ns++)
                    #pragma unroll
                    for (int q = 0; q < 4; q++) c[ms][ns][q] = 0.f;

            #pragma unroll
            for (int s = 0; s < 8; s++) {
                uint32_t A[2][4];
                #pragma unroll
                for (int ms = 0; ms < 2; ms++) {
                    uint32_t addr = hs_base + (uint32_t)((i0 + ms * 16 + arow_l) * HS_STRIDE_B
                                                         + (2 * s + asel) * 16);
                    ldmx4(A[ms][0], A[ms][1], A[ms][2], A[ms][3], addr);
                }
                #pragma unroll
                for (int ms = 0; ms < 2; ms++)
                    #pragma unroll
                    for (int ns = 0; ns < 4; ns++) {
                        uint32_t bb0 = Ball[s][(ns >> 1) * 4 + ((ns & 1) ? 2 : 0)];
                        uint32_t bb1 = Ball[s][(ns >> 1) * 4 + ((ns & 1) ? 3 : 1)];
                        mma_bf16(c[ms][ns][0], c[ms][ns][1], c[ms][ns][2], c[ms][ns][3],
                                 A[ms][0], A[ms][1], A[ms][2], A[ms][3], bb0, bb1);
                    }
            }

            if (rt < b) {
                #pragma unroll
                for (int ms = 0; ms < 2; ms++) {
                    #pragma unroll
                    for (int ns = 0; ns < 4; ns++) {
                        const int i  = i0 + ms * 16 + gq;
                        const int j  = j0 + ns * 8 + 2 * tq;
                        const float sj0 = sq[j], sj1 = sq[j + 1];
                        float si = sq[i];
                        float d0 = sqrt_ap(fmaxf(si + sj0 - 2.f * c[ms][ns][0], 0.f) + 1e-12f);
                        float d1 = sqrt_ap(fmaxf(si + sj1 - 2.f * c[ms][ns][1], 0.f) + 1e-12f);
                        *(__half2*)&Dg[i * 256 + j] = __floats2half2_rn(d0, d1);
                        float si8 = sq[i + 8];
                        float d2 = sqrt_ap(fmaxf(si8 + sj0 - 2.f * c[ms][ns][2], 0.f) + 1e-12f);
                        float d3 = sqrt_ap(fmaxf(si8 + sj1 - 2.f * c[ms][ns][3], 0.f) + 1e-12f);
                        *(__half2*)&Dg[(i + 8) * 256 + j] = __floats2half2_rn(d2, d3);
                        sumD += 2.f * (d0 + d1 + d2 + d3);
                    }
                }
            } else {
                // diagonal tile: write jj >= i-7 (alignment slack for pass 2), weight only jj>=i
                #pragma unroll
                for (int ms = 0; ms < 2; ms++) {
                    #pragma unroll
                    for (int ns = 0; ns < 4; ns++) {
                        const int jj = j0 + ns * 8 + 2 * tq;
                        const float sj0 = sq[jj], sj1 = sq[jj + 1];
                        #pragma unroll
                        for (int h = 0; h < 2; h++) {
                            const int i = i0 + ms * 16 + gq + 8 * h;
                            const float si = sq[i];
                            const float cv0 = c[ms][ns][2 * h], cv1 = c[ms][ns][2 * h + 1];
                            if (jj >= i - 7) {
                                float d0 = sqrt_ap(fmaxf(si + sj0 - 2.f * cv0, 0.f) + 1e-12f);
                                Dg[i * 256 + jj] = __float2half(d0);
                                if (jj >= i) sumD += (jj > i) ? 2.f * d0 : d0;
                            }
                            if (jj + 1 >= i - 7) {
                                float d1 = sqrt_ap(fmaxf(si + sj1 - 2.f * cv1, 0.f) + 1e-12f);
                                Dg[i * 256 + jj + 1] = __float2half(d1);
                                if (jj + 1 >= i) sumD += (jj + 1 > i) ? 2.f * d1 : d1;
                            }
                        }
                    }
                }
            }
        }
    }

    // reduce sumD
    #pragma unroll
    for (int o = 16; o; o >>= 1) sumD += __shfl_xor_sync(0xffffffffu, sumD, o);
    if (lane == 0) red[wid] = sumD;
    __syncthreads();
    float meanD = 0.f;
    #pragma unroll
    for (int w = 0; w < 8; w++) meanD += red[w];
    meanD *= (1.f / 65536.f);

    // ================== pass 2: coalesced chunks, packed fp16 center-out chain ==================
    const float invf = 1.f / ((meanD + 1e-8f) * 0.1875f);
    const __half2 inv2  = __float2half2_rn(invf);
    const __half2 off2  = __float2half2_rn(-5.3333333f);
    const __half2 A2    = __float2half2_rn(-0.72134752f);
    const __half2 RHO2  = __float2half2_rn(1.53887471f);
    const __half2 ONE2  = __float2half2_rn(1.0f);
    const __half2 UMAX2 = __float2half2_rn(5.4f);
    const __half2 UMIN2 = __float2half2_rn(-5.4f);
    // step ratio m=1..5: 2^{-0.820734*(2m-1)}  (cumulative product reproduces CKS exactly)
    const __half2 RS2[5] = { __float2half2_rn(0.566155f),  __float2half2_rn(0.181456f),
                             __float2half2_rn(0.0581705f), __float2half2_rn(0.0186443f),
                             __float2half2_rn(0.00597603f) };

    float histf[NB];
    #pragma unroll
    for (int k = 0; k < NB; k++) histf[k] = 0.f;

    const char* Dgb = (const char*)Dg;
    for (int it = 0; it < 17; it++) {
        int w = it * 256 + tid;
        if (w >= NCHUNK) break;
        // decode chunk -> (row r, chunk col c); f(q) = 260q - 4q^2
        int q = (int)((65.f - sqrtf(4225.f - (float)w)) * 0.5f);
        if (260 * (q + 1) - 4 * (q + 1) * (q + 1) <= w) q++;
        if (260 * q - 4 * q * q > w) q--;
        int rem = w - (260 * q - 4 * q * q);
        int cnt = 32 - q;
        int ro  = rem / cnt;
        int r   = q * 8 + ro;
        int c   = q + (rem - ro * cnt);

        uint4 vv = *(const uint4*)(Dgb + r * 512 + c * 16);
        __half2 dd[4] = { *(__half2*)&vv.x, *(__half2*)&vv.y, *(__half2*)&vv.z, *(__half2*)&vv.w };

        __half2 wl[4];
        if (c == q) {               // chunk contains/abuts the diagonal: per-element log2-weights
            int jb = c * 8;
            #pragma unroll
            for (int e = 0; e < 4; e++) {
                int jl = jb + 2 * e;
                float wlo = (jl     > r) ? 1.f : ((jl     == r) ? 0.f : -300.f);
                float whi = (jl + 1 > r) ? 1.f : ((jl + 1 == r) ? 0.f : -300.f);
                wl[e] = __floats2half2_rn(wlo, whi);
            }
        } else {
            #pragma unroll
            for (int e = 0; e < 4; e++) wl[e] = ONE2;   // strictly upper: weight 2 (log2 = 1)
        }

        __half2 h2a[NB];
        #pragma unroll
        for (int k = 0; k < NB; k++) h2a[k] = __float2half2_rn(0.f);

        #pragma unroll
        for (int e = 0; e < 4; e++) {
            __half2 u2 = __hfma2(dd[e], inv2, off2);
            u2 = __hmax2(__hmin2(u2, UMAX2), UMIN2);    // |pu| <= 8.31 -> P,Pi <= 317, no inf
            __half2 us = __hmul2(u2, u2);
            __half2 e0 = __hfma2(us, A2, wl[e]);
            __half2 w5 = h2ex2(e0);                     // <= 2
            __half2 pu = __hmul2(u2, RHO2);
            __half2 P  = h2ex2(pu);
            __half2 Pi = h2ex2(__hneg2(pu));
            h2a[5] = __hadd2(h2a[5], w5);
            __half2 rr = w5;
            #pragma unroll
            for (int m = 0; m < 5; m++) {               // bins 4..0 (intermediates = true weights <= 2)
                rr = __hmul2(__hmul2(rr, Pi), RS2[m]);
                h2a[4 - m] = __hadd2(h2a[4 - m], rr);
            }
            rr = w5;
            #pragma unroll
            for (int m = 0; m < 5; m++) {               // bins 6..10
                rr = __hmul2(__hmul2(rr, P), RS2[m]);
                h2a[6 + m] = __hadd2(h2a[6 + m], rr);
            }
        }
        // flush chunk (8 elements) to f32 accumulators
        #pragma unroll
        for (int k = 0; k < NB; k++) {
            float2 t = __half22float2(h2a[k]);
            histf[k] += t.x + t.y;
        }
    }

    // reduce hist, write signature
    #pragma unroll
    for (int k = 0; k < NB; k++)
        #pragma unroll
        for (int o = 16; o; o >>= 1)
            histf[k] += __shfl_xor_sync(0xffffffffu, histf[k], o);
    if (lane == 0) {
        #pragma unroll
        for (int k = 0; k < NB; k++) red[8 + wid * NB + k] = histf[k];
    }
    __syncthreads();

    if (tid < KB) {
        float h = 0.f;
        if (tid < NB) {
            #pragma unroll
            for (int w = 0; w < 8; w++) h += red[8 + w * NB + tid];
        }
        float tot = h;
        #pragma unroll
        for (int o = 8; o; o >>= 1) tot += __shfl_xor_sync(0x0000ffffu, tot, o);
        g_sig[bx * KB + tid] = h / (tot + 1e-8f);
    }
    __syncthreads();

    // ================== NT-Xent row bx ==================
    {
        float* invn = sq;
        const float* zp = (tid < G) ? (z1 + tid * DF) : (z2 + (tid - G) * DF);
        const float4* zp4 = (const float4*)zp;
        float s = 0.f;
        #pragma unroll 8
        for (int k = 0; k < 32; k++) {
            float4 a = zp4[k];
            s = fmaf(a.x, a.x, fmaf(a.y, a.y, fmaf(a.z, a.z, fmaf(a.w, a.w, s))));
        }
        invn[tid] = 1.f / (sqrtf(s) + 1e-8f);

        const float* zrp = (bx < G) ? (z1 + bx * DF) : (z2 + (bx - G) * DF);
        if (tid < 32) ((float4*)zr)[tid] = ((const float4*)zrp)[tid];
        __syncthreads();

        float dot = 0.f;
        const float4* zr4 = (const float4*)zr;
        #pragma unroll 8
        for (int k = 0; k < 32; k++) {
            float4 a = zp4[k], b2 = zr4[k];
            dot = fmaf(a.x, b2.x, fmaf(a.y, b2.y, fmaf(a.z, b2.z, fmaf(a.w, b2.w, dot))));
        }
        float sim = dot * invn[bx] * invn[tid] * 2.0f;
        const int lbl = bx ^ G;
        if (tid == lbl) red[120] = sim;

        float e = (tid == bx) ? 0.f : __expf(sim);
        #pragma unroll
        for (int o = 16; o; o >>= 1) e += __shfl_xor_sync(0xffffffffu, e, o);
        __syncthreads();
        if (lane == 0) red[wid] = e;
        __syncthreads();
        if (tid == 0) {
            float S = 0.f;
            #pragma unroll
            for (int w = 0; w < 8; w++) S += red[w];
            g_rowloss[bx] = __logf(S) - red[120];
        }
    }

    // ================== last CTA: final reduction ==================
    __shared__ unsigned amLast;
    __syncthreads();
    if (tid == 0) {
        __threadfence();
        unsigned vv = atomicInc(&g_ctr, 255);
        amLast = (vv == 255) ? 1u : 0u;
    }
    __syncthreads();

    if (amLast) {
        __threadfence();
        float a = 0.f;
        for (int idx = tid; idx < G * KB; idx += 256) {
            float d = g_sig[idx] - g_sig[G * KB + idx];
            a += d * d;
        }
        a *= (1.f / 2048.f);
        a += g_rowloss[tid] * (1.f / 256.f);
        #pragma unroll
        for (int o = 16; o; o >>= 1) a += __shfl_xor_sync(0xffffffffu, a, o);
        if (lane == 0) red[64 + wid] = a;
        __syncthreads();
        if (tid == 0) {
            float t = 0.f;
            #pragma unroll
            for (int w = 0; w < 8; w++) t += red[64 + w];
            out[0] = 0.1f * t;
        }
    }
}

extern "C" void kernel_launch(void* const* d_in, const int* in_sizes, int n_in,
                              void* d_out, int out_size)
{
    const float* H1 = (const float*)d_in[0];
    const float* H2 = (const float*)d_in[2];
    const float* z1 = (const float*)d_in[4];
    const float* z2 = (const float*)d_in[5];
    float* out = (float*)d_out;

    cudaFuncSetAttribute(uts_kernel, cudaFuncAttributeMaxDynamicSharedMemorySize, SMEM_A);
    uts_kernel<<<256, 256, SMEM_A>>>(H1, H2, z1, z2, out);
}